// round 13
// baseline (speedup 1.0000x reference)
#include <cuda_runtime.h>

// YOLO loss reduction: prediction/target (16384, 6, 6, 106) fp32 -> 6 fp32 scalars.
// Single fused kernel (last-block-finishes). R10 profile: DRAM 71.7%, issue 64.8%
// -> instruction-throttled. This version loads each cell-PAIR as 53 float4
// (848 B, 16B-aligned): 4 LDG.128 per lane instead of 8 LDG.64 -> half the load
// instructions + half the address math. Channel map straddles cells at lanes
// 0, 1, 26, 27 only; conf broadcasts from lane 1 (cell A) and lane 27 (cell B).
// Deterministic block combine -> 5 partials/block -> last block reduces in
// fixed order (bitwise deterministic), finalizes, resets counter (replay-safe).

#define CH 106
#define F4_PER_PAIR 53
#define GRID_BLOCKS 4736
#define WARPS_PER_BLOCK 8
#define BLOCK_THREADS 256
#define FULL_ROUNDS (GRID_BLOCKS / BLOCK_THREADS)              // 18
#define TAIL_COUNT (GRID_BLOCKS - FULL_ROUNDS * BLOCK_THREADS) // 128

__device__ float g_part[5][GRID_BLOCKS];   // per-block partials (SoA)
__device__ unsigned int g_count = 0;       // self-resetting arrival counter

// float2-based single-cell path (tail only; dead for the benched shape)
struct CellErr { float xy, wh, conf, cls, tc; };

__device__ __forceinline__ CellErr cell_compute2(
    int lane, float2 t0, float2 p0, float2 t1, float2 p1)
{
    CellErr e{0.f, 0.f, 0.f, 0.f, 0.f};
    const float d0 = t0.x - p0.x;
    const float d1 = t0.y - p0.y;
    if (lane == 0) {
        e.xy = d0 * d0 + d1 * d1;
    } else if (lane == 1) {
        float s0 = sqrtf(t0.x) - sqrtf(fmaxf(p0.x, 0.f));
        float s1 = sqrtf(t0.y) - sqrtf(fmaxf(p0.y, 0.f));
        e.wh = s0 * s0 + s1 * s1;
    } else if (lane == 2) {
        e.tc = t0.x;
        e.conf = d0 * d0;
        e.cls = d1 * d1;
    } else {
        e.cls = d0 * d0 + d1 * d1;
    }
    const float d2 = t1.x - p1.x;
    const float d3 = t1.y - p1.y;
    e.cls += d2 * d2 + d3 * d3;
    return e;
}

__global__ void __launch_bounds__(BLOCK_THREADS, 6) yolo_loss_kernel(
    const float* __restrict__ pred,
    const float* __restrict__ targ,
    int n_cells,
    float invB,
    float* __restrict__ out)
{
    const int lane = threadIdx.x & 31;
    const int wib  = threadIdx.x >> 5;
    const int warp_id = blockIdx.x * WARPS_PER_BLOCK + wib;
    const int n_warps = gridDim.x * WARPS_PER_BLOCK;

    float a_xy = 0.f, a_wh = 0.f, a_co = 0.f, a_cn = 0.f, a_cls = 0.f;

    const bool has2 = (lane < F4_PER_PAIR - 32);   // lanes 0..20 do pass 1
    const float4 z4 = make_float4(0.f, 0.f, 0.f, 0.f);

    const int n_pairs = n_cells >> 1;

    for (int pair = warp_id; pair < n_pairs; pair += n_warps) {
        const float4* __restrict__ tq = (const float4*)(targ + (size_t)pair * (2 * CH));
        const float4* __restrict__ pq = (const float4*)(pred + (size_t)pair * (2 * CH));

        // front-batch all 4 LDG.128 before any math
        float4 t0 = tq[lane];
        float4 p0 = pq[lane];
        float4 t1 = has2 ? tq[32 + lane] : z4;
        float4 p1 = has2 ? pq[32 + lane] : z4;

        // per-lane contributions to cell A / cell B components
        float exyA = 0.f, ewhA = 0.f, ecoA = 0.f, eclsA = 0.f, tcA = 0.f;
        float exyB = 0.f, ewhB = 0.f, ecoB = 0.f, eclsB = 0.f, tcB = 0.f;

        const float d0 = t0.x - p0.x;
        const float d1 = t0.y - p0.y;
        const float d2 = t0.z - p0.z;
        const float d3 = t0.w - p0.w;

        if (lane == 0) {                     // g 0-3: A xy (0,1), A wh (2,3)
            exyA = d0 * d0 + d1 * d1;
            float s0 = sqrtf(t0.z) - sqrtf(fmaxf(p0.z, 0.f));
            float s1 = sqrtf(t0.w) - sqrtf(fmaxf(p0.w, 0.f));
            ewhA = s0 * s0 + s1 * s1;
        } else if (lane == 1) {              // g 4-7: A conf (4), A cls (5,6,7)
            tcA = t0.x;
            ecoA = d0 * d0;
            eclsA = d1 * d1 + d2 * d2 + d3 * d3;
        } else if (lane == 26) {             // g 104-107: A cls (104,105), B xy (106,107)
            eclsA = d0 * d0 + d1 * d1;
            exyB = d2 * d2 + d3 * d3;
        } else if (lane == 27) {             // g 108-111: B wh (108,109), B conf (110), B cls (111)
            float s0 = sqrtf(t0.x) - sqrtf(fmaxf(p0.x, 0.f));
            float s1 = sqrtf(t0.y) - sqrtf(fmaxf(p0.y, 0.f));
            ewhB = s0 * s0 + s1 * s1;
            tcB = t0.z;
            ecoB = d2 * d2;
            eclsB = d3 * d3;
        } else if (lane < 26) {              // lanes 2-25: A cls x4
            eclsA = d0 * d0 + d1 * d1 + d2 * d2 + d3 * d3;
        } else {                             // lanes 28-31: B cls x4
            eclsB = d0 * d0 + d1 * d1 + d2 * d2 + d3 * d3;
        }

        // pass 1 (g 128-211): all B class (zeros for lanes >= 21)
        const float e0 = t1.x - p1.x;
        const float e1 = t1.y - p1.y;
        const float e2 = t1.z - p1.z;
        const float e3 = t1.w - p1.w;
        eclsB += e0 * e0 + e1 * e1 + e2 * e2 + e3 * e3;

        // object masks: A conf lives on lane 1 (.x), B conf on lane 27 (.z)
        const float tconfA = __shfl_sync(0xffffffffu, tcA, 1);
        const float tconfB = __shfl_sync(0xffffffffu, tcB, 27);
        const float objA = (tconfA != 0.f) ? 1.f : 0.f;
        const float objB = (tconfB != 0.f) ? 1.f : 0.f;

        a_xy  += objA * exyA + objB * exyB;
        a_wh  += objA * ewhA + objB * ewhB;
        a_co  += objA * ecoA + objB * ecoB;
        a_cn  += (1.f - objA) * ecoA + (1.f - objB) * ecoB;
        a_cls += objA * eclsA + objB * eclsB;
    }

    // odd tail cell (dead for benched shape, kept for generality): warp 0 only
    if ((n_cells & 1) && warp_id == 0) {
        const int cell = n_cells - 1;
        const float2* __restrict__ tp = (const float2*)(targ + (size_t)cell * CH);
        const float2* __restrict__ pp = (const float2*)(pred + (size_t)cell * CH);
        const bool h2 = (lane < 21);
        const float2 z2 = make_float2(0.f, 0.f);
        float2 t0 = tp[lane];
        float2 p0 = pp[lane];
        float2 t1 = h2 ? tp[32 + lane] : z2;
        float2 p1 = h2 ? pp[32 + lane] : z2;
        CellErr e = cell_compute2(lane, t0, p0, t1, p1);
        const float tc = __shfl_sync(0xffffffffu, e.tc, 2);
        const float obj = (tc != 0.f) ? 1.f : 0.f;
        a_xy  += obj * e.xy;
        a_wh  += obj * e.wh;
        a_cls += obj * e.cls;
        a_co  += obj * e.conf;
        a_cn  += (1.f - obj) * e.conf;
    }

    // warp tree-reduce (deterministic shuffle order)
    #pragma unroll
    for (int off = 16; off > 0; off >>= 1) {
        a_xy  += __shfl_xor_sync(0xffffffffu, a_xy,  off);
        a_wh  += __shfl_xor_sync(0xffffffffu, a_wh,  off);
        a_co  += __shfl_xor_sync(0xffffffffu, a_co,  off);
        a_cn  += __shfl_xor_sync(0xffffffffu, a_cn,  off);
        a_cls += __shfl_xor_sync(0xffffffffu, a_cls, off);
    }

    // deterministic block combine: per-warp slots, fixed-order sum
    __shared__ float s_warp[WARPS_PER_BLOCK][5];
    if (lane == 0) {
        s_warp[wib][0] = a_xy;
        s_warp[wib][1] = a_wh;
        s_warp[wib][2] = a_co;
        s_warp[wib][3] = a_cn;
        s_warp[wib][4] = a_cls;
    }
    __syncthreads();

    if (threadIdx.x < 5) {
        float s = 0.f;
        #pragma unroll
        for (int w = 0; w < WARPS_PER_BLOCK; w++) s += s_warp[w][threadIdx.x];
        g_part[threadIdx.x][blockIdx.x] = s;
    }

    // ---- last-block-finishes final reduction ----
    __shared__ bool s_is_last;
    __threadfence();
    if (threadIdx.x == 0) {
        unsigned int prev = atomicAdd(&g_count, 1u);
        s_is_last = (prev == (unsigned int)(gridDim.x - 1));
    }
    __syncthreads();
    if (!s_is_last) return;

    __threadfence();

    const int tid = threadIdx.x;

    // fixed traversal order -> bitwise deterministic regardless of last block
    float acc[5] = {0.f, 0.f, 0.f, 0.f, 0.f};
    #pragma unroll
    for (int k = 0; k < FULL_ROUNDS; k++) {
        const int i = tid + k * BLOCK_THREADS;
        #pragma unroll
        for (int c = 0; c < 5; c++) acc[c] += g_part[c][i];
    }
    if (tid < TAIL_COUNT) {
        const int i = tid + FULL_ROUNDS * BLOCK_THREADS;
        #pragma unroll
        for (int c = 0; c < 5; c++) acc[c] += g_part[c][i];
    }

    #pragma unroll
    for (int off = 16; off > 0; off >>= 1) {
        #pragma unroll
        for (int c = 0; c < 5; c++)
            acc[c] += __shfl_xor_sync(0xffffffffu, acc[c], off);
    }

    __shared__ float s_fin[WARPS_PER_BLOCK][5];
    if (lane == 0) {
        #pragma unroll
        for (int c = 0; c < 5; c++) s_fin[wib][c] = acc[c];
    }
    __syncthreads();

    if (tid == 0) {
        float tot[5];
        #pragma unroll
        for (int c = 0; c < 5; c++) {
            float s = 0.f;
            #pragma unroll
            for (int w = 0; w < WARPS_PER_BLOCK; w++) s += s_fin[w][c];
            tot[c] = s * invB;
        }
        out[0] = tot[0];
        out[1] = tot[1];
        out[2] = tot[2];
        out[3] = tot[3];
        out[4] = tot[4];
        out[5] = (5.0f * tot[0] + 5.0f * tot[1] + tot[2]
                  + 0.5f * tot[3] + tot[4]) * invB;

        g_count = 0;                               // reset for next replay
    }
}

extern "C" void kernel_launch(void* const* d_in, const int* in_sizes, int n_in,
                              void* d_out, int out_size)
{
    const float* pred = (const float*)d_in[0];
    const float* targ = (const float*)d_in[1];
    float* out = (float*)d_out;

    const int n_cells = in_sizes[0] / CH;          // 16384 * 36 = 589824
    const int B = n_cells / 36;                    // batch = 16384 (S=6)
    const float invB = 1.0f / (float)B;

    yolo_loss_kernel<<<GRID_BLOCKS, BLOCK_THREADS>>>(pred, targ, n_cells, invB, out);
}

// round 14
// speedup vs baseline: 1.1666x; 1.1666x over previous
#include <cuda_runtime.h>

// YOLO loss reduction: prediction/target (16384, 6, 6, 106) fp32 -> 6 fp32 scalars.
// Fused single kernel (last-block-finishes). Base = R10 float2 warp-per-pair
// (measured 88.2us, DRAM 71.7%, issue 64.8%). R13 float4 variant REGRESSED
// (100.4us, issue UP) -> diagnosis: divergent role-branches (BSSY/BSYNC regions)
// are the instruction sink, not loads. This version makes the hot loop fully
// BRANCHLESS: loop-invariant per-lane float masks + weighted FMAs, wh via the
// identity (sqrt(w)-sqrt(v))^2 = w+v-2*sqrt(w*v) with sqrt.approx.f32 (1 MUFU
// per element), conf mask via bare shfl from lane 2.
// Deterministic everywhere: warp shuffle-reduce -> per-warp shared slots ->
// fixed-order block sum -> per-block partials -> last block reduces in fixed
// traversal order, finalizes, resets counter (replay/graph safe, no FP atomics).

#define CH 106
#define F2_PER_CELL 53
#define GRID_BLOCKS 4736
#define WARPS_PER_BLOCK 8
#define BLOCK_THREADS 256
#define FULL_ROUNDS (GRID_BLOCKS / BLOCK_THREADS)              // 18
#define TAIL_COUNT (GRID_BLOCKS - FULL_ROUNDS * BLOCK_THREADS) // 128

__device__ float g_part[5][GRID_BLOCKS];   // per-block partials (SoA)
__device__ unsigned int g_count = 0;       // self-resetting arrival counter

__device__ __forceinline__ float sqrt_approx(float x) {
    float r;
    asm("sqrt.approx.f32 %0, %1;" : "=f"(r) : "f"(x));
    return r;
}

__global__ void __launch_bounds__(BLOCK_THREADS) yolo_loss_kernel(
    const float* __restrict__ pred,
    const float* __restrict__ targ,
    int n_cells,
    float invB,
    float* __restrict__ out)
{
    const int lane = threadIdx.x & 31;
    const int wib  = threadIdx.x >> 5;
    const int warp_id = blockIdx.x * WARPS_PER_BLOCK + wib;
    const int n_warps = gridDim.x * WARPS_PER_BLOCK;

    // loop-invariant per-lane role masks (channel 2L, 2L+1 on lane L, pass 0)
    const float m_xy   = (lane == 0) ? 1.f : 0.f;  // ch0,1
    const float m_wh   = (lane == 1) ? 1.f : 0.f;  // ch2,3
    const float m_cf   = (lane == 2) ? 1.f : 0.f;  // ch4 (x elem)
    const float m_clsx = (lane >= 3) ? 1.f : 0.f;  // x elem is class
    const float m_clsy = (lane >= 2) ? 1.f : 0.f;  // y elem is class (ch5 on lane2)

    const bool has2 = (lane < F2_PER_CELL - 32);   // lanes 0..20 do pass 1
    const float2 z2 = make_float2(0.f, 0.f);

    float a_xy = 0.f, a_wh = 0.f, a_co = 0.f, a_cn = 0.f, a_cls = 0.f;

    const int n_pairs = n_cells >> 1;

    for (int pair = warp_id; pair < n_pairs; pair += n_warps) {
        const size_t base = (size_t)pair * (2 * CH);
        const float2* __restrict__ tpa = (const float2*)(targ + base);
        const float2* __restrict__ ppa = (const float2*)(pred + base);
        const float2* __restrict__ tpb = (const float2*)(targ + base + CH);
        const float2* __restrict__ ppb = (const float2*)(pred + base + CH);

        // front-batch all 8 loads (both cells) before any math
        float2 ta0 = tpa[lane];
        float2 pa0 = ppa[lane];
        float2 tb0 = tpb[lane];
        float2 pb0 = ppb[lane];
        float2 ta1 = has2 ? tpa[32 + lane] : z2;
        float2 pa1 = has2 ? ppa[32 + lane] : z2;
        float2 tb1 = has2 ? tpb[32 + lane] : z2;
        float2 pb1 = has2 ? ppb[32 + lane] : z2;

        // object masks first (independent shfl, overlaps with math below)
        const float tcA = __shfl_sync(0xffffffffu, ta0.x, 2);
        const float tcB = __shfl_sync(0xffffffffu, tb0.x, 2);
        const float objA = (tcA != 0.f) ? 1.f : 0.f;
        const float objB = (tcB != 0.f) ? 1.f : 0.f;

        // ---- cell A (branchless) ----
        {
            const float d0 = ta0.x - pa0.x;
            const float d1 = ta0.y - pa0.y;
            const float q0 = d0 * d0;
            const float q1 = d1 * d1;
            // wh via identity: (sqrt(w)-sqrt(v))^2 = w + v - 2*sqrt(w*v), w,v>=0
            const float pc0 = fmaxf(pa0.x, 0.f);
            const float pc1 = fmaxf(pa0.y, 0.f);
            const float wh = (ta0.x + pc0 - 2.f * sqrt_approx(ta0.x * pc0))
                           + (ta0.y + pc1 - 2.f * sqrt_approx(ta0.y * pc1));
            const float e0 = ta1.x - pa1.x;
            const float e1 = ta1.y - pa1.y;
            const float cls1 = e0 * e0 + e1 * e1;           // pass-1: all class

            const float nobjA = 1.f - objA;
            a_xy  = fmaf(m_xy * objA, q0 + q1, a_xy);
            a_wh  = fmaf(m_wh * objA, wh, a_wh);
            a_co  = fmaf(m_cf * objA, q0, a_co);
            a_cn  = fmaf(m_cf * nobjA, q0, a_cn);
            const float clsA = fmaf(m_clsx, q0, fmaf(m_clsy, q1, cls1));
            a_cls = fmaf(objA, clsA, a_cls);
        }

        // ---- cell B (branchless) ----
        {
            const float d0 = tb0.x - pb0.x;
            const float d1 = tb0.y - pb0.y;
            const float q0 = d0 * d0;
            const float q1 = d1 * d1;
            const float pc0 = fmaxf(pb0.x, 0.f);
            const float pc1 = fmaxf(pb0.y, 0.f);
            const float wh = (tb0.x + pc0 - 2.f * sqrt_approx(tb0.x * pc0))
                           + (tb0.y + pc1 - 2.f * sqrt_approx(tb0.y * pc1));
            const float e0 = tb1.x - pb1.x;
            const float e1 = tb1.y - pb1.y;
            const float cls1 = e0 * e0 + e1 * e1;

            const float nobjB = 1.f - objB;
            a_xy  = fmaf(m_xy * objB, q0 + q1, a_xy);
            a_wh  = fmaf(m_wh * objB, wh, a_wh);
            a_co  = fmaf(m_cf * objB, q0, a_co);
            a_cn  = fmaf(m_cf * nobjB, q0, a_cn);
            const float clsB = fmaf(m_clsx, q0, fmaf(m_clsy, q1, cls1));
            a_cls = fmaf(objB, clsB, a_cls);
        }
    }

    // odd tail cell (dead for benched shape): warp 0, branchless same scheme
    if ((n_cells & 1) && warp_id == 0) {
        const int cell = n_cells - 1;
        const float2* __restrict__ tp = (const float2*)(targ + (size_t)cell * CH);
        const float2* __restrict__ pp = (const float2*)(pred + (size_t)cell * CH);
        float2 t0 = tp[lane];
        float2 p0 = pp[lane];
        float2 t1 = has2 ? tp[32 + lane] : z2;
        float2 p1 = has2 ? pp[32 + lane] : z2;

        const float tc = __shfl_sync(0xffffffffu, t0.x, 2);
        const float obj = (tc != 0.f) ? 1.f : 0.f;

        const float d0 = t0.x - p0.x;
        const float d1 = t0.y - p0.y;
        const float q0 = d0 * d0;
        const float q1 = d1 * d1;
        const float pc0 = fmaxf(p0.x, 0.f);
        const float pc1 = fmaxf(p0.y, 0.f);
        const float wh = (t0.x + pc0 - 2.f * sqrt_approx(t0.x * pc0))
                       + (t0.y + pc1 - 2.f * sqrt_approx(t0.y * pc1));
        const float e0 = t1.x - p1.x;
        const float e1 = t1.y - p1.y;
        const float cls1 = e0 * e0 + e1 * e1;

        a_xy  = fmaf(m_xy * obj, q0 + q1, a_xy);
        a_wh  = fmaf(m_wh * obj, wh, a_wh);
        a_co  = fmaf(m_cf * obj, q0, a_co);
        a_cn  = fmaf(m_cf * (1.f - obj), q0, a_cn);
        a_cls = fmaf(obj, fmaf(m_clsx, q0, fmaf(m_clsy, q1, cls1)), a_cls);
    }

    // warp tree-reduce (deterministic shuffle order)
    #pragma unroll
    for (int off = 16; off > 0; off >>= 1) {
        a_xy  += __shfl_xor_sync(0xffffffffu, a_xy,  off);
        a_wh  += __shfl_xor_sync(0xffffffffu, a_wh,  off);
        a_co  += __shfl_xor_sync(0xffffffffu, a_co,  off);
        a_cn  += __shfl_xor_sync(0xffffffffu, a_cn,  off);
        a_cls += __shfl_xor_sync(0xffffffffu, a_cls, off);
    }

    // deterministic block combine: per-warp slots, fixed-order sum
    __shared__ float s_warp[WARPS_PER_BLOCK][5];
    if (lane == 0) {
        s_warp[wib][0] = a_xy;
        s_warp[wib][1] = a_wh;
        s_warp[wib][2] = a_co;
        s_warp[wib][3] = a_cn;
        s_warp[wib][4] = a_cls;
    }
    __syncthreads();

    if (threadIdx.x < 5) {
        float s = 0.f;
        #pragma unroll
        for (int w = 0; w < WARPS_PER_BLOCK; w++) s += s_warp[w][threadIdx.x];
        g_part[threadIdx.x][blockIdx.x] = s;
    }

    // ---- last-block-finishes final reduction ----
    __shared__ bool s_is_last;
    __threadfence();
    if (threadIdx.x == 0) {
        unsigned int prev = atomicAdd(&g_count, 1u);
        s_is_last = (prev == (unsigned int)(gridDim.x - 1));
    }
    __syncthreads();
    if (!s_is_last) return;

    __threadfence();

    const int tid = threadIdx.x;

    // fixed traversal order -> bitwise deterministic regardless of last block
    float acc[5] = {0.f, 0.f, 0.f, 0.f, 0.f};
    #pragma unroll
    for (int k = 0; k < FULL_ROUNDS; k++) {
        const int i = tid + k * BLOCK_THREADS;
        #pragma unroll
        for (int c = 0; c < 5; c++) acc[c] += g_part[c][i];
    }
    if (tid < TAIL_COUNT) {
        const int i = tid + FULL_ROUNDS * BLOCK_THREADS;
        #pragma unroll
        for (int c = 0; c < 5; c++) acc[c] += g_part[c][i];
    }

    #pragma unroll
    for (int off = 16; off > 0; off >>= 1) {
        #pragma unroll
        for (int c = 0; c < 5; c++)
            acc[c] += __shfl_xor_sync(0xffffffffu, acc[c], off);
    }

    __shared__ float s_fin[WARPS_PER_BLOCK][5];
    if (lane == 0) {
        #pragma unroll
        for (int c = 0; c < 5; c++) s_fin[wib][c] = acc[c];
    }
    __syncthreads();

    if (tid == 0) {
        float tot[5];
        #pragma unroll
        for (int c = 0; c < 5; c++) {
            float s = 0.f;
            #pragma unroll
            for (int w = 0; w < WARPS_PER_BLOCK; w++) s += s_fin[w][c];
            tot[c] = s * invB;
        }
        out[0] = tot[0];
        out[1] = tot[1];
        out[2] = tot[2];
        out[3] = tot[3];
        out[4] = tot[4];
        out[5] = (5.0f * tot[0] + 5.0f * tot[1] + tot[2]
                  + 0.5f * tot[3] + tot[4]) * invB;

        g_count = 0;                               // reset for next replay
    }
}

extern "C" void kernel_launch(void* const* d_in, const int* in_sizes, int n_in,
                              void* d_out, int out_size)
{
    const float* pred = (const float*)d_in[0];
    const float* targ = (const float*)d_in[1];
    float* out = (float*)d_out;

    const int n_cells = in_sizes[0] / CH;          // 16384 * 36 = 589824
    const int B = n_cells / 36;                    // batch = 16384 (S=6)
    const float invB = 1.0f / (float)B;

    yolo_loss_kernel<<<GRID_BLOCKS, BLOCK_THREADS>>>(pred, targ, n_cells, invB, out);
}